// round 13
// baseline (speedup 1.0000x reference)
#include <cuda_runtime.h>
#include <cstdint>

#define NN 50000
#define EE 600000
#define DD 128
#define NEG 0.2f
#define SCAN_B 256
#define NB_SCAN ((NN + SCAN_B - 1) / SCAN_B)   // 196

#define FLAG_A 0x40000000u
#define FLAG_P 0x80000000u
#define VAL_M  0x3FFFFFFFu

// bf16 GEMM smem layout (uint32 units)
#define AP_STRIDE 68     // 64 k-pairs + 4 pad
#define WP_STRIDE 136    // 128 n + 8 pad
#define A_HI_OFF  0
#define A_LO_OFF  (64 * AP_STRIDE)
#define W_HI_OFF  (2 * 64 * AP_STRIDE)
#define W_LO_OFF  (W_HI_OFF + 64 * WP_STRIDE)
#define SMEM_U32  (W_LO_OFF + 64 * WP_STRIDE)   // 26112 u32 = 104448 B

// Scratch (device globals: zero-initialized at module load; kernels maintain
// the zero-invariant for cnt/state/ticket across calls)
__device__ int      g_cnt[NN];
__device__ int      g_cur[NN];
__device__ int      g_rowptr[NN + 1];
__device__ int      g_src[EE];
__device__ unsigned g_state[NB_SCAN];
__device__ int      g_ticket;
__device__ float    g_dis[NN];
__device__ float    g_hw [NN * DD];   // scaled: (A@W)[i,:] * dis[i]
__device__ float    g_h  [NN * DD];
__device__ uint32_t g_whi[3][64 * 128];   // pre-split W per layer (hi bf16x2)
__device__ uint32_t g_wlo[3][64 * 128];   // pre-split W per layer (lo bf16x2)

__global__ void k_count(const int* __restrict__ col, int* __restrict__ cnt, int ne) {
    int e = blockIdx.x * blockDim.x + threadIdx.x;
    if (e < ne) atomicAdd(&cnt[col[e]], 1);
}

// fused exclusive scan (decoupled lookback) + dis + cur seeding; re-zeroes cnt
__global__ void __launch_bounds__(SCAN_B) k_scan(int* __restrict__ cnt,
                                                 int* __restrict__ rowptr,
                                                 int* __restrict__ cur,
                                                 float* __restrict__ dis,
                                                 unsigned* __restrict__ state,
                                                 int* __restrict__ ticket,
                                                 int n, int ne) {
    __shared__ int sh[SCAN_B];
    __shared__ int sh_bid;
    __shared__ int sh_off;
    int t = threadIdx.x;
    if (t == 0) sh_bid = atomicAdd(ticket, 1);
    __syncthreads();
    int bid = sh_bid;
    int i = bid * SCAN_B + t;
    int v = 0;
    if (i < n) {
        v = cnt[i];
        cnt[i] = 0;
        dis[i] = rsqrtf((float)v + 1.f);
    }
    sh[t] = v; __syncthreads();
#pragma unroll
    for (int o = 1; o < SCAN_B; o <<= 1) {
        int x = (t >= o) ? sh[t - o] : 0;
        __syncthreads();
        sh[t] += x;
        __syncthreads();
    }
    int agg = sh[SCAN_B - 1];

    if (t == 0 && bid > 0) {
        __threadfence();
        atomicExch(&state[bid], FLAG_A | (unsigned)agg);
    }
    if (t < 32) {
        int off = 0;
        if (bid > 0) {
            int p = bid - 1;
            while (p >= 0) {
                int idx = p - t;
                bool valid = idx >= 0;
                unsigned s = 0;
                do {
                    if (valid) s = atomicAdd(&state[idx], 0u);
                } while (__any_sync(0xffffffffu, valid && s == 0u));
                unsigned pm = __ballot_sync(0xffffffffu, valid && (s & FLAG_P));
                int contrib;
                if (pm) {
                    int firstP = __ffs(pm) - 1;
                    contrib = (valid && t <= firstP) ? (int)(s & VAL_M) : 0;
                } else {
                    contrib = valid ? (int)(s & VAL_M) : 0;
                }
#pragma unroll
                for (int o = 16; o > 0; o >>= 1)
                    contrib += __shfl_xor_sync(0xffffffffu, contrib, o);
                off += contrib;
                if (pm) break;
                p -= 32;
            }
        }
        if (t == 0) {
            __threadfence();
            atomicExch(&state[bid], FLAG_P | (unsigned)(off + agg));
            sh_off = off;
        }
    }
    __syncthreads();
    int off = sh_off;
    if (i < n) {
        int r = off + sh[t] - v;
        rowptr[i] = r;
        cur[i] = r;
    }
    if (bid == NB_SCAN - 1 && t == 0) rowptr[n] = ne;
}

// bucket edges; also restores state/ticket zero-invariant (safe: runs after scan)
__global__ void k_bucket(const int* __restrict__ row, const int* __restrict__ col,
                         int* __restrict__ cur, int* __restrict__ src,
                         unsigned* __restrict__ state, int* __restrict__ ticket, int ne) {
    int e = blockIdx.x * blockDim.x + threadIdx.x;
    if (e < NB_SCAN) state[e] = 0u;
    if (e == 0) *ticket = 0;
    if (e >= ne) return;
    int p = atomicAdd(&cur[col[e]], 1);
    src[p] = row[e];
}

// ---------------- bf16 split helpers ----------------
__device__ __forceinline__ void split_pack(float x0, float x1, uint32_t& hi, uint32_t& lo) {
    asm("cvt.rn.bf16x2.f32 %0, %1, %2;" : "=r"(hi) : "f"(x1), "f"(x0));
    float h0 = __uint_as_float(hi << 16);
    float h1 = __uint_as_float(hi & 0xFFFF0000u);
    float l0 = x0 - h0;
    float l1 = x1 - h1;
    asm("cvt.rn.bf16x2.f32 %0, %1, %2;" : "=r"(lo) : "f"(l1), "f"(l0));
}

// pre-split one weight matrix W[128,128] into [64 kp][128 n] hi/lo
__global__ void k_splitw(const float* __restrict__ W, uint32_t* __restrict__ whi,
                         uint32_t* __restrict__ wlo) {
    int idx = blockIdx.x * blockDim.x + threadIdx.x;   // 0..8191
    int kp = idx >> 7;
    int n  = idx & 127;
    float w0 = W[(2 * kp) * 128 + n];
    float w1 = W[(2 * kp + 1) * 128 + n];
    uint32_t h, l;
    split_pack(w0, w1, h, l);
    whi[idx] = h;
    wlo[idx] = l;
}

__device__ __forceinline__ void mma16(float* d, const uint32_t* a, uint32_t b0, uint32_t b1) {
    asm volatile(
        "mma.sync.aligned.m16n8k16.row.col.f32.bf16.bf16.f32 "
        "{%0,%1,%2,%3}, {%4,%5,%6,%7}, {%8,%9}, {%0,%1,%2,%3};"
        : "+f"(d[0]), "+f"(d[1]), "+f"(d[2]), "+f"(d[3])
        : "r"(a[0]), "r"(a[1]), "r"(a[2]), "r"(a[3]), "r"(b0), "r"(b1));
}

// ---------------- GEMM: C[i,:] = (A[i,:] @ W) * dis[i], 3xBF16 ----------------
// Block 64x128, 256 threads, warp tile 32x32, 2 CTAs/SM. W arrives pre-split.
__global__ void __launch_bounds__(256, 2) k_gemm(const float* __restrict__ A,
                                                 const uint32_t* __restrict__ whi_g,
                                                 const uint32_t* __restrict__ wlo_g,
                                                 const float* __restrict__ dis,
                                                 float* __restrict__ C, int nrows) {
    extern __shared__ uint32_t sm[];
    uint32_t* Ahi = sm + A_HI_OFF;
    uint32_t* Alo = sm + A_LO_OFF;
    uint32_t* Whi = sm + W_HI_OFF;
    uint32_t* Wlo = sm + W_LO_OFF;

    int t    = threadIdx.x;
    int lane = t & 31;
    int wid  = t >> 5;
    int warp_m = wid & 1;
    int warp_n = wid >> 1;
    int q  = lane >> 2;
    int r4 = lane & 3;
    int row0 = blockIdx.x * 64;

    // ---- pre-split A tile: 64 rows x 64 k-pairs ----
    const float2* A2 = (const float2*)A;
#pragma unroll
    for (int i = 0; i < 16; i++) {
        int idx = i * 256 + t;
        int r  = idx >> 6;
        int kp = idx & 63;
        int gr = row0 + r;
        float2 v = (gr < nrows) ? A2[gr * 64 + kp] : make_float2(0.f, 0.f);
        uint32_t h, l;
        split_pack(v.x, v.y, h, l);
        Ahi[r * AP_STRIDE + kp] = h;
        Alo[r * AP_STRIDE + kp] = l;
    }
    // ---- copy pre-split W (vectorized, no conversion): 2048 uint4 per array ----
    const uint4* wh4 = (const uint4*)whi_g;
    const uint4* wl4 = (const uint4*)wlo_g;
#pragma unroll
    for (int i = 0; i < 8; i++) {
        int idx = i * 256 + t;                // 0..2047 uint4
        int kp = idx >> 5;                    // 0..63
        int n4 = idx & 31;
        *(uint4*)&Whi[kp * WP_STRIDE + n4 * 4] = wh4[idx];
        *(uint4*)&Wlo[kp * WP_STRIDE + n4 * 4] = wl4[idx];
    }
    __syncthreads();

    float acc[2][4][4];
#pragma unroll
    for (int mt = 0; mt < 2; mt++)
#pragma unroll
        for (int nt = 0; nt < 4; nt++)
#pragma unroll
            for (int j = 0; j < 4; j++) acc[mt][nt][j] = 0.f;

#pragma unroll 2
    for (int ks = 0; ks < 8; ks++) {
        int kb = ks * 8;
        uint32_t ah[2][4], al[2][4];
#pragma unroll
        for (int mt = 0; mt < 2; mt++) {
            int ra = (warp_m * 32 + mt * 16 + q) * AP_STRIDE;
            int rb = ra + 8 * AP_STRIDE;
            ah[mt][0] = Ahi[ra + kb + r4];
            ah[mt][1] = Ahi[rb + kb + r4];
            ah[mt][2] = Ahi[ra + kb + r4 + 4];
            ah[mt][3] = Ahi[rb + kb + r4 + 4];
            al[mt][0] = Alo[ra + kb + r4];
            al[mt][1] = Alo[rb + kb + r4];
            al[mt][2] = Alo[ra + kb + r4 + 4];
            al[mt][3] = Alo[rb + kb + r4 + 4];
        }
        uint32_t bh[4][2], bl[4][2];
#pragma unroll
        for (int nt = 0; nt < 4; nt++) {
            int n = warp_n * 32 + nt * 8 + q;
            bh[nt][0] = Whi[(kb + r4) * WP_STRIDE + n];
            bh[nt][1] = Whi[(kb + r4 + 4) * WP_STRIDE + n];
            bl[nt][0] = Wlo[(kb + r4) * WP_STRIDE + n];
            bl[nt][1] = Wlo[(kb + r4 + 4) * WP_STRIDE + n];
        }
#pragma unroll
        for (int mt = 0; mt < 2; mt++)
#pragma unroll
            for (int nt = 0; nt < 4; nt++) {
                mma16(acc[mt][nt], ah[mt], bh[nt][0], bh[nt][1]);
                mma16(acc[mt][nt], al[mt], bh[nt][0], bh[nt][1]);
                mma16(acc[mt][nt], ah[mt], bl[nt][0], bl[nt][1]);
            }
    }

#pragma unroll
    for (int mt = 0; mt < 2; mt++) {
        int ra = row0 + warp_m * 32 + mt * 16 + q;
        int rb = ra + 8;
        float da = (ra < nrows) ? dis[ra] : 0.f;
        float db = (rb < nrows) ? dis[rb] : 0.f;
#pragma unroll
        for (int nt = 0; nt < 4; nt++) {
            int colb = warp_n * 32 + nt * 8 + r4 * 2;
            if (ra < nrows)
                *(float2*)&C[ra * 128 + colb] = make_float2(acc[mt][nt][0] * da, acc[mt][nt][1] * da);
            if (rb < nrows)
                *(float2*)&C[rb * 128 + colb] = make_float2(acc[mt][nt][2] * db, acc[mt][nt][3] * db);
        }
    }
}

// ---------------- pull core (MLP=2, pure adds over pre-scaled rows) ----------------
__device__ __forceinline__ float4 pull_acc(const int* __restrict__ src,
                                           const float* __restrict__ hw,
                                           int s0, int s1, int lane) {
    float4 acc = make_float4(0.f, 0.f, 0.f, 0.f);
    int j = s0;
    for (; j + 1 < s1; j += 2) {
        int sA = src[j], sB = src[j + 1];
        float4 vA = ((const float4*)hw)[sA * 32 + lane];
        float4 vB = ((const float4*)hw)[sB * 32 + lane];
        acc.x += vA.x + vB.x; acc.y += vA.y + vB.y;
        acc.z += vA.z + vB.z; acc.w += vA.w + vB.w;
    }
    if (j < s1) {
        int s = src[j];
        float4 v = ((const float4*)hw)[s * 32 + lane];
        acc.x += v.x; acc.y += v.y; acc.z += v.z; acc.w += v.w;
    }
    return acc;
}

__global__ void __launch_bounds__(256) k_pull(const int* __restrict__ rowptr,
                                              const int* __restrict__ src,
                                              const float* __restrict__ dis,
                                              const float* __restrict__ hw,
                                              const float* __restrict__ b,
                                              const float* __restrict__ hprev,
                                              float* __restrict__ hout, int n, int residual) {
    int gid  = blockIdx.x * blockDim.x + threadIdx.x;
    int node = gid >> 5;
    int lane = gid & 31;
    if (node >= n) return;
    float4 acc = pull_acc(src, hw, rowptr[node], rowptr[node + 1], lane);
    float d = dis[node];
    float4 hv = ((const float4*)hw)[node * 32 + lane];
    float4 bv = ((const float4*)b)[lane];
    float4 o;
    o.x = (acc.x + hv.x) * d + bv.x;
    o.y = (acc.y + hv.y) * d + bv.y;
    o.z = (acc.z + hv.z) * d + bv.z;
    o.w = (acc.w + hv.w) * d + bv.w;
    if (residual) {
        float4 p = ((const float4*)hprev)[node * 32 + lane];
        o.x += p.x; o.y += p.y; o.z += p.z; o.w += p.w;
    }
    o.x = (o.x > 0.f) ? o.x : NEG * o.x;
    o.y = (o.y > 0.f) ? o.y : NEG * o.y;
    o.z = (o.z > 0.f) ? o.z : NEG * o.z;
    o.w = (o.w > 0.f) ? o.w : NEG * o.w;
    ((float4*)hout)[node * 32 + lane] = o;
}

__global__ void __launch_bounds__(256) k_pull_logits(const int* __restrict__ rowptr,
                                                     const int* __restrict__ src,
                                                     const float* __restrict__ dis,
                                                     const float* __restrict__ hw,
                                                     const float* __restrict__ b,
                                                     const float* __restrict__ hprev,
                                                     const float* __restrict__ lw,
                                                     const float* __restrict__ lb,
                                                     float* __restrict__ out, int n) {
    int gid  = blockIdx.x * blockDim.x + threadIdx.x;
    int node = gid >> 5;
    int lane = gid & 31;
    if (node >= n) return;
    float4 acc = pull_acc(src, hw, rowptr[node], rowptr[node + 1], lane);
    float d = dis[node];
    float4 hv = ((const float4*)hw)[node * 32 + lane];
    float4 bv = ((const float4*)b)[lane];
    float4 p  = ((const float4*)hprev)[node * 32 + lane];
    float4 o;
    o.x = (acc.x + hv.x) * d + bv.x + p.x;
    o.y = (acc.y + hv.y) * d + bv.y + p.y;
    o.z = (acc.z + hv.z) * d + bv.z + p.z;
    o.w = (acc.w + hv.w) * d + bv.w + p.w;
    o.x = (o.x > 0.f) ? o.x : NEG * o.x;
    o.y = (o.y > 0.f) ? o.y : NEG * o.y;
    o.z = (o.z > 0.f) ? o.z : NEG * o.z;
    o.w = (o.w > 0.f) ? o.w : NEG * o.w;
    float4 wv = ((const float4*)lw)[lane];
    float s = o.x * wv.x + o.y * wv.y + o.z * wv.z + o.w * wv.w;
#pragma unroll
    for (int off = 16; off > 0; off >>= 1) s += __shfl_down_sync(0xffffffffu, s, off);
    if (lane == 0) out[node] = s + lb[0];
}

extern "C" void kernel_launch(void* const* d_in, const int* in_sizes, int n_in,
                              void* d_out, int out_size) {
    const float* x   = (const float*)d_in[0];
    const int*   ei  = (const int*)d_in[1];
    const float* W1  = (const float*)d_in[2];
    const float* b1  = (const float*)d_in[3];
    const float* W2  = (const float*)d_in[4];
    const float* b2  = (const float*)d_in[5];
    const float* W3  = (const float*)d_in[6];
    const float* b3  = (const float*)d_in[7];
    const float* lw  = (const float*)d_in[8];
    const float* lb  = (const float*)d_in[9];
    float* out = (float*)d_out;

    const int ne = in_sizes[1] / 2;      // 600000
    const int n  = in_sizes[0] / DD;     // 50000
    const int* row = ei;
    const int* col = ei + ne;

    int *cnt, *cur, *rowptr, *src, *ticket;
    unsigned* state;
    float *dis, *hw, *h;
    uint32_t *whi, *wlo;
    cudaGetSymbolAddress((void**)&cnt,    g_cnt);
    cudaGetSymbolAddress((void**)&cur,    g_cur);
    cudaGetSymbolAddress((void**)&rowptr, g_rowptr);
    cudaGetSymbolAddress((void**)&src,    g_src);
    cudaGetSymbolAddress((void**)&state,  g_state);
    cudaGetSymbolAddress((void**)&ticket, g_ticket);
    cudaGetSymbolAddress((void**)&dis,    g_dis);
    cudaGetSymbolAddress((void**)&hw,     g_hw);
    cudaGetSymbolAddress((void**)&h,      g_h);
    cudaGetSymbolAddress((void**)&whi,    g_whi);
    cudaGetSymbolAddress((void**)&wlo,    g_wlo);

    cudaFuncSetAttribute(k_gemm, cudaFuncAttributeMaxDynamicSharedMemorySize,
                         SMEM_U32 * sizeof(uint32_t));

    const int T = 256;
    int gemm_grid = (n + 63) / 64;
    int pull_grid = (int)(((long long)n * 32 + T - 1) / T);
    size_t smem   = SMEM_U32 * sizeof(uint32_t);

    // fork-join resources
    cudaStream_t s1;
    cudaEvent_t ev_start, ev_scan, ev_g1;
    cudaStreamCreateWithFlags(&s1, cudaStreamNonBlocking);
    cudaEventCreateWithFlags(&ev_start, cudaEventDisableTiming);
    cudaEventCreateWithFlags(&ev_scan, cudaEventDisableTiming);
    cudaEventCreateWithFlags(&ev_g1, cudaEventDisableTiming);

    // ---- legal capture fork: s1's FIRST op is a wait on a stream-0 event ----
    cudaEventRecord(ev_start, 0);
    cudaStreamWaitEvent(s1, ev_start, 0);

    // ---- side stream: pre-split all 3 weight matrices (overlaps CSC build) ----
    k_splitw<<<32, T, 0, s1>>>(W1, whi + 0 * 8192, wlo + 0 * 8192);
    k_splitw<<<32, T, 0, s1>>>(W2, whi + 1 * 8192, wlo + 1 * 8192);
    k_splitw<<<32, T, 0, s1>>>(W3, whi + 2 * 8192, wlo + 2 * 8192);

    // ---- CSC build on stream 0 ----
    k_count<<<(ne + T - 1) / T, T>>>(col, cnt, ne);
    k_scan <<<NB_SCAN, SCAN_B>>>(cnt, rowptr, cur, dis, state, ticket, n, ne);
    cudaEventRecord(ev_scan, 0);
    k_bucket<<<(ne + T - 1) / T, T>>>(row, col, cur, src, state, ticket, ne);

    // ---- layer-1 GEMM on s1 (after splitw in-order + dis via ev_scan), overlaps bucket ----
    cudaStreamWaitEvent(s1, ev_scan, 0);
    k_gemm<<<gemm_grid, T, smem, s1>>>(x, whi + 0 * 8192, wlo + 0 * 8192, dis, hw, n);
    cudaEventRecord(ev_g1, s1);
    cudaStreamWaitEvent(0, ev_g1, 0);

    // ---- layer 1 pull ----
    k_pull<<<pull_grid, T>>>(rowptr, src, dis, hw, b1, nullptr, h, n, 0);

    // ---- layer 2 ----
    k_gemm<<<gemm_grid, T, smem>>>(h, whi + 1 * 8192, wlo + 1 * 8192, dis, hw, n);
    k_pull<<<pull_grid, T>>>(rowptr, src, dis, hw, b2, h, h, n, 1);

    // ---- layer 3 (fused with logits head) ----
    k_gemm<<<gemm_grid, T, smem>>>(h, whi + 2 * 8192, wlo + 2 * 8192, dis, hw, n);
    k_pull_logits<<<pull_grid, T>>>(rowptr, src, dis, hw, b3, h, lw, lb, out, n);
}

// round 14
// speedup vs baseline: 1.0301x; 1.0301x over previous
#include <cuda_runtime.h>
#include <cstdint>

#define NN 50000
#define EE 600000
#define DD 128
#define NEG 0.2f
#define SCAN_B 256
#define NB_SCAN ((NN + SCAN_B - 1) / SCAN_B)   // 196

#define FLAG_A 0x40000000u
#define FLAG_P 0x80000000u
#define VAL_M  0x3FFFFFFFu

// bf16 GEMM smem layout (uint32 units)
#define AP_STRIDE 68     // 64 k-pairs + 4 pad
#define WP_STRIDE 136    // 128 n + 8 pad
#define A_HI_OFF  0
#define A_LO_OFF  (64 * AP_STRIDE)
#define W_HI_OFF  (2 * 64 * AP_STRIDE)
#define W_LO_OFF  (W_HI_OFF + 64 * WP_STRIDE)
#define SMEM_U32  (W_LO_OFF + 64 * WP_STRIDE)   // 26112 u32 = 104448 B

#define GEMM_GRID 296    // 148 SMs x 2 CTAs/SM, single resident wave
#define NTILES ((NN + 63) / 64)   // 782

// Scratch (device globals: zero-initialized at module load; kernels maintain
// the zero-invariant for cnt/state/ticket across calls)
__device__ int      g_cnt[NN];
__device__ int      g_cur[NN];
__device__ int      g_rowptr[NN + 1];
__device__ int      g_src[EE];
__device__ unsigned g_state[NB_SCAN];
__device__ int      g_ticket;
__device__ float    g_dis[NN];
__device__ float    g_hw [NN * DD];   // scaled: (A@W)[i,:] * dis[i]
__device__ float    g_h  [NN * DD];
__device__ uint32_t g_whi[3][64 * 128];   // pre-split W per layer (hi bf16x2)
__device__ uint32_t g_wlo[3][64 * 128];   // pre-split W per layer (lo bf16x2)

__global__ void k_count(const int* __restrict__ col, int* __restrict__ cnt, int ne) {
    int e = blockIdx.x * blockDim.x + threadIdx.x;
    if (e < ne) atomicAdd(&cnt[col[e]], 1);
}

// fused exclusive scan (decoupled lookback) + dis + cur seeding; re-zeroes cnt
__global__ void __launch_bounds__(SCAN_B) k_scan(int* __restrict__ cnt,
                                                 int* __restrict__ rowptr,
                                                 int* __restrict__ cur,
                                                 float* __restrict__ dis,
                                                 unsigned* __restrict__ state,
                                                 int* __restrict__ ticket,
                                                 int n, int ne) {
    __shared__ int sh[SCAN_B];
    __shared__ int sh_bid;
    __shared__ int sh_off;
    int t = threadIdx.x;
    if (t == 0) sh_bid = atomicAdd(ticket, 1);
    __syncthreads();
    int bid = sh_bid;
    int i = bid * SCAN_B + t;
    int v = 0;
    if (i < n) {
        v = cnt[i];
        cnt[i] = 0;
        dis[i] = rsqrtf((float)v + 1.f);
    }
    sh[t] = v; __syncthreads();
#pragma unroll
    for (int o = 1; o < SCAN_B; o <<= 1) {
        int x = (t >= o) ? sh[t - o] : 0;
        __syncthreads();
        sh[t] += x;
        __syncthreads();
    }
    int agg = sh[SCAN_B - 1];

    if (t == 0 && bid > 0) {
        __threadfence();
        atomicExch(&state[bid], FLAG_A | (unsigned)agg);
    }
    if (t < 32) {
        int off = 0;
        if (bid > 0) {
            int p = bid - 1;
            while (p >= 0) {
                int idx = p - t;
                bool valid = idx >= 0;
                unsigned s = 0;
                do {
                    if (valid) s = atomicAdd(&state[idx], 0u);
                } while (__any_sync(0xffffffffu, valid && s == 0u));
                unsigned pm = __ballot_sync(0xffffffffu, valid && (s & FLAG_P));
                int contrib;
                if (pm) {
                    int firstP = __ffs(pm) - 1;
                    contrib = (valid && t <= firstP) ? (int)(s & VAL_M) : 0;
                } else {
                    contrib = valid ? (int)(s & VAL_M) : 0;
                }
#pragma unroll
                for (int o = 16; o > 0; o >>= 1)
                    contrib += __shfl_xor_sync(0xffffffffu, contrib, o);
                off += contrib;
                if (pm) break;
                p -= 32;
            }
        }
        if (t == 0) {
            __threadfence();
            atomicExch(&state[bid], FLAG_P | (unsigned)(off + agg));
            sh_off = off;
        }
    }
    __syncthreads();
    int off = sh_off;
    if (i < n) {
        int r = off + sh[t] - v;
        rowptr[i] = r;
        cur[i] = r;
    }
    if (bid == NB_SCAN - 1 && t == 0) rowptr[n] = ne;
}

// bucket edges; also restores state/ticket zero-invariant (safe: runs after scan)
__global__ void k_bucket(const int* __restrict__ row, const int* __restrict__ col,
                         int* __restrict__ cur, int* __restrict__ src,
                         unsigned* __restrict__ state, int* __restrict__ ticket, int ne) {
    int e = blockIdx.x * blockDim.x + threadIdx.x;
    if (e < NB_SCAN) state[e] = 0u;
    if (e == 0) *ticket = 0;
    if (e >= ne) return;
    int p = atomicAdd(&cur[col[e]], 1);
    src[p] = row[e];
}

// ---------------- bf16 split helpers ----------------
__device__ __forceinline__ void split_pack(float x0, float x1, uint32_t& hi, uint32_t& lo) {
    asm("cvt.rn.bf16x2.f32 %0, %1, %2;" : "=r"(hi) : "f"(x1), "f"(x0));
    float h0 = __uint_as_float(hi << 16);
    float h1 = __uint_as_float(hi & 0xFFFF0000u);
    float l0 = x0 - h0;
    float l1 = x1 - h1;
    asm("cvt.rn.bf16x2.f32 %0, %1, %2;" : "=r"(lo) : "f"(l1), "f"(l0));
}

// pre-split one weight matrix W[128,128] into [64 kp][128 n] hi/lo
__global__ void k_splitw(const float* __restrict__ W, uint32_t* __restrict__ whi,
                         uint32_t* __restrict__ wlo) {
    int idx = blockIdx.x * blockDim.x + threadIdx.x;   // 0..8191
    int kp = idx >> 7;
    int n  = idx & 127;
    float w0 = W[(2 * kp) * 128 + n];
    float w1 = W[(2 * kp + 1) * 128 + n];
    uint32_t h, l;
    split_pack(w0, w1, h, l);
    whi[idx] = h;
    wlo[idx] = l;
}

__device__ __forceinline__ void mma16(float* d, const uint32_t* a, uint32_t b0, uint32_t b1) {
    asm volatile(
        "mma.sync.aligned.m16n8k16.row.col.f32.bf16.bf16.f32 "
        "{%0,%1,%2,%3}, {%4,%5,%6,%7}, {%8,%9}, {%0,%1,%2,%3};"
        : "+f"(d[0]), "+f"(d[1]), "+f"(d[2]), "+f"(d[3])
        : "r"(a[0]), "r"(a[1]), "r"(a[2]), "r"(a[3]), "r"(b0), "r"(b1));
}

// ---------------- persistent GEMM: C[i,:] = (A[i,:] @ W) * dis[i], 3xBF16 ----
// Grid 296 (one resident wave). W loaded into smem ONCE per CTA; loop over
// 64-row tiles. Block 256 threads, warp tile 32x32, 2 CTAs/SM.
__global__ void __launch_bounds__(256, 2) k_gemm(const float* __restrict__ A,
                                                 const uint32_t* __restrict__ whi_g,
                                                 const uint32_t* __restrict__ wlo_g,
                                                 const float* __restrict__ dis,
                                                 float* __restrict__ C, int nrows) {
    extern __shared__ uint32_t sm[];
    uint32_t* Ahi = sm + A_HI_OFF;
    uint32_t* Alo = sm + A_LO_OFF;
    uint32_t* Whi = sm + W_HI_OFF;
    uint32_t* Wlo = sm + W_LO_OFF;

    int t    = threadIdx.x;
    int lane = t & 31;
    int wid  = t >> 5;
    int warp_m = wid & 1;
    int warp_n = wid >> 1;
    int q  = lane >> 2;
    int r4 = lane & 3;

    // ---- load pre-split W ONCE: 2048 uint4 per array ----
    const uint4* wh4 = (const uint4*)whi_g;
    const uint4* wl4 = (const uint4*)wlo_g;
#pragma unroll
    for (int i = 0; i < 8; i++) {
        int idx = i * 256 + t;                // 0..2047 uint4
        int kp = idx >> 5;                    // 0..63
        int n4 = idx & 31;
        *(uint4*)&Whi[kp * WP_STRIDE + n4 * 4] = wh4[idx];
        *(uint4*)&Wlo[kp * WP_STRIDE + n4 * 4] = wl4[idx];
    }

    const float2* A2 = (const float2*)A;
    int ntiles = (nrows + 63) >> 6;

    for (int tile = blockIdx.x; tile < ntiles; tile += gridDim.x) {
        int row0 = tile * 64;
        __syncthreads();   // prev tile's mma reads done (also covers W load on iter 0)

        // ---- split A tile: 64 rows x 64 k-pairs ----
#pragma unroll
        for (int i = 0; i < 16; i++) {
            int idx = i * 256 + t;
            int r  = idx >> 6;
            int kp = idx & 63;
            int gr = row0 + r;
            float2 v = (gr < nrows) ? A2[gr * 64 + kp] : make_float2(0.f, 0.f);
            uint32_t h, l;
            split_pack(v.x, v.y, h, l);
            Ahi[r * AP_STRIDE + kp] = h;
            Alo[r * AP_STRIDE + kp] = l;
        }
        __syncthreads();

        float acc[2][4][4];
#pragma unroll
        for (int mt = 0; mt < 2; mt++)
#pragma unroll
            for (int nt = 0; nt < 4; nt++)
#pragma unroll
                for (int j = 0; j < 4; j++) acc[mt][nt][j] = 0.f;

#pragma unroll 2
        for (int ks = 0; ks < 8; ks++) {
            int kb = ks * 8;
            uint32_t ah[2][4], al[2][4];
#pragma unroll
            for (int mt = 0; mt < 2; mt++) {
                int ra = (warp_m * 32 + mt * 16 + q) * AP_STRIDE;
                int rb = ra + 8 * AP_STRIDE;
                ah[mt][0] = Ahi[ra + kb + r4];
                ah[mt][1] = Ahi[rb + kb + r4];
                ah[mt][2] = Ahi[ra + kb + r4 + 4];
                ah[mt][3] = Ahi[rb + kb + r4 + 4];
                al[mt][0] = Alo[ra + kb + r4];
                al[mt][1] = Alo[rb + kb + r4];
                al[mt][2] = Alo[ra + kb + r4 + 4];
                al[mt][3] = Alo[rb + kb + r4 + 4];
            }
            uint32_t bh[4][2], bl[4][2];
#pragma unroll
            for (int nt = 0; nt < 4; nt++) {
                int n = warp_n * 32 + nt * 8 + q;
                bh[nt][0] = Whi[(kb + r4) * WP_STRIDE + n];
                bh[nt][1] = Whi[(kb + r4 + 4) * WP_STRIDE + n];
                bl[nt][0] = Wlo[(kb + r4) * WP_STRIDE + n];
                bl[nt][1] = Wlo[(kb + r4 + 4) * WP_STRIDE + n];
            }
#pragma unroll
            for (int mt = 0; mt < 2; mt++)
#pragma unroll
                for (int nt = 0; nt < 4; nt++) {
                    mma16(acc[mt][nt], ah[mt], bh[nt][0], bh[nt][1]);
                    mma16(acc[mt][nt], al[mt], bh[nt][0], bh[nt][1]);
                    mma16(acc[mt][nt], ah[mt], bl[nt][0], bl[nt][1]);
                }
        }

#pragma unroll
        for (int mt = 0; mt < 2; mt++) {
            int ra = row0 + warp_m * 32 + mt * 16 + q;
            int rb = ra + 8;
            float da = (ra < nrows) ? dis[ra] : 0.f;
            float db = (rb < nrows) ? dis[rb] : 0.f;
#pragma unroll
            for (int nt = 0; nt < 4; nt++) {
                int colb = warp_n * 32 + nt * 8 + r4 * 2;
                if (ra < nrows)
                    *(float2*)&C[ra * 128 + colb] = make_float2(acc[mt][nt][0] * da, acc[mt][nt][1] * da);
                if (rb < nrows)
                    *(float2*)&C[rb * 128 + colb] = make_float2(acc[mt][nt][2] * db, acc[mt][nt][3] * db);
            }
        }
    }
}

// ---------------- pull core (MLP=2, pure adds over pre-scaled rows) ----------------
__device__ __forceinline__ float4 pull_acc(const int* __restrict__ src,
                                           const float* __restrict__ hw,
                                           int s0, int s1, int lane) {
    float4 acc = make_float4(0.f, 0.f, 0.f, 0.f);
    int j = s0;
    for (; j + 1 < s1; j += 2) {
        int sA = src[j], sB = src[j + 1];
        float4 vA = ((const float4*)hw)[sA * 32 + lane];
        float4 vB = ((const float4*)hw)[sB * 32 + lane];
        acc.x += vA.x + vB.x; acc.y += vA.y + vB.y;
        acc.z += vA.z + vB.z; acc.w += vA.w + vB.w;
    }
    if (j < s1) {
        int s = src[j];
        float4 v = ((const float4*)hw)[s * 32 + lane];
        acc.x += v.x; acc.y += v.y; acc.z += v.z; acc.w += v.w;
    }
    return acc;
}

__global__ void __launch_bounds__(256) k_pull(const int* __restrict__ rowptr,
                                              const int* __restrict__ src,
                                              const float* __restrict__ dis,
                                              const float* __restrict__ hw,
                                              const float* __restrict__ b,
                                              const float* __restrict__ hprev,
                                              float* __restrict__ hout, int n, int residual) {
    int gid  = blockIdx.x * blockDim.x + threadIdx.x;
    int node = gid >> 5;
    int lane = gid & 31;
    if (node >= n) return;
    float4 acc = pull_acc(src, hw, rowptr[node], rowptr[node + 1], lane);
    float d = dis[node];
    float4 hv = ((const float4*)hw)[node * 32 + lane];
    float4 bv = ((const float4*)b)[lane];
    float4 o;
    o.x = (acc.x + hv.x) * d + bv.x;
    o.y = (acc.y + hv.y) * d + bv.y;
    o.z = (acc.z + hv.z) * d + bv.z;
    o.w = (acc.w + hv.w) * d + bv.w;
    if (residual) {
        float4 p = ((const float4*)hprev)[node * 32 + lane];
        o.x += p.x; o.y += p.y; o.z += p.z; o.w += p.w;
    }
    o.x = (o.x > 0.f) ? o.x : NEG * o.x;
    o.y = (o.y > 0.f) ? o.y : NEG * o.y;
    o.z = (o.z > 0.f) ? o.z : NEG * o.z;
    o.w = (o.w > 0.f) ? o.w : NEG * o.w;
    ((float4*)hout)[node * 32 + lane] = o;
}

__global__ void __launch_bounds__(256) k_pull_logits(const int* __restrict__ rowptr,
                                                     const int* __restrict__ src,
                                                     const float* __restrict__ dis,
                                                     const float* __restrict__ hw,
                                                     const float* __restrict__ b,
                                                     const float* __restrict__ hprev,
                                                     const float* __restrict__ lw,
                                                     const float* __restrict__ lb,
                                                     float* __restrict__ out, int n) {
    int gid  = blockIdx.x * blockDim.x + threadIdx.x;
    int node = gid >> 5;
    int lane = gid & 31;
    if (node >= n) return;
    float4 acc = pull_acc(src, hw, rowptr[node], rowptr[node + 1], lane);
    float d = dis[node];
    float4 hv = ((const float4*)hw)[node * 32 + lane];
    float4 bv = ((const float4*)b)[lane];
    float4 p  = ((const float4*)hprev)[node * 32 + lane];
    float4 o;
    o.x = (acc.x + hv.x) * d + bv.x + p.x;
    o.y = (acc.y + hv.y) * d + bv.y + p.y;
    o.z = (acc.z + hv.z) * d + bv.z + p.z;
    o.w = (acc.w + hv.w) * d + bv.w + p.w;
    o.x = (o.x > 0.f) ? o.x : NEG * o.x;
    o.y = (o.y > 0.f) ? o.y : NEG * o.y;
    o.z = (o.z > 0.f) ? o.z : NEG * o.z;
    o.w = (o.w > 0.f) ? o.w : NEG * o.w;
    float4 wv = ((const float4*)lw)[lane];
    float s = o.x * wv.x + o.y * wv.y + o.z * wv.z + o.w * wv.w;
#pragma unroll
    for (int off = 16; off > 0; off >>= 1) s += __shfl_down_sync(0xffffffffu, s, off);
    if (lane == 0) out[node] = s + lb[0];
}

extern "C" void kernel_launch(void* const* d_in, const int* in_sizes, int n_in,
                              void* d_out, int out_size) {
    const float* x   = (const float*)d_in[0];
    const int*   ei  = (const int*)d_in[1];
    const float* W1  = (const float*)d_in[2];
    const float* b1  = (const float*)d_in[3];
    const float* W2  = (const float*)d_in[4];
    const float* b2  = (const float*)d_in[5];
    const float* W3  = (const float*)d_in[6];
    const float* b3  = (const float*)d_in[7];
    const float* lw  = (const float*)d_in[8];
    const float* lb  = (const float*)d_in[9];
    float* out = (float*)d_out;

    const int ne = in_sizes[1] / 2;      // 600000
    const int n  = in_sizes[0] / DD;     // 50000
    const int* row = ei;
    const int* col = ei + ne;

    int *cnt, *cur, *rowptr, *src, *ticket;
    unsigned* state;
    float *dis, *hw, *h;
    uint32_t *whi, *wlo;
    cudaGetSymbolAddress((void**)&cnt,    g_cnt);
    cudaGetSymbolAddress((void**)&cur,    g_cur);
    cudaGetSymbolAddress((void**)&rowptr, g_rowptr);
    cudaGetSymbolAddress((void**)&src,    g_src);
    cudaGetSymbolAddress((void**)&state,  g_state);
    cudaGetSymbolAddress((void**)&ticket, g_ticket);
    cudaGetSymbolAddress((void**)&dis,    g_dis);
    cudaGetSymbolAddress((void**)&hw,     g_hw);
    cudaGetSymbolAddress((void**)&h,      g_h);
    cudaGetSymbolAddress((void**)&whi,    g_whi);
    cudaGetSymbolAddress((void**)&wlo,    g_wlo);

    cudaFuncSetAttribute(k_gemm, cudaFuncAttributeMaxDynamicSharedMemorySize,
                         SMEM_U32 * sizeof(uint32_t));

    const int T = 256;
    int pull_grid = (int)(((long long)n * 32 + T - 1) / T);
    size_t smem   = SMEM_U32 * sizeof(uint32_t);

    // fork-join resources
    cudaStream_t s1;
    cudaEvent_t ev_start, ev_scan, ev_g1;
    cudaStreamCreateWithFlags(&s1, cudaStreamNonBlocking);
    cudaEventCreateWithFlags(&ev_start, cudaEventDisableTiming);
    cudaEventCreateWithFlags(&ev_scan, cudaEventDisableTiming);
    cudaEventCreateWithFlags(&ev_g1, cudaEventDisableTiming);

    // ---- legal capture fork: s1's FIRST op is a wait on a stream-0 event ----
    cudaEventRecord(ev_start, 0);
    cudaStreamWaitEvent(s1, ev_start, 0);

    // ---- side stream: pre-split all 3 weight matrices (overlaps CSC build) ----
    k_splitw<<<32, T, 0, s1>>>(W1, whi + 0 * 8192, wlo + 0 * 8192);
    k_splitw<<<32, T, 0, s1>>>(W2, whi + 1 * 8192, wlo + 1 * 8192);
    k_splitw<<<32, T, 0, s1>>>(W3, whi + 2 * 8192, wlo + 2 * 8192);

    // ---- CSC build on stream 0 ----
    k_count<<<(ne + T - 1) / T, T>>>(col, cnt, ne);
    k_scan <<<NB_SCAN, SCAN_B>>>(cnt, rowptr, cur, dis, state, ticket, n, ne);
    cudaEventRecord(ev_scan, 0);
    k_bucket<<<(ne + T - 1) / T, T>>>(row, col, cur, src, state, ticket, ne);

    // ---- layer-1 GEMM on s1 (after splitw in-order + dis via ev_scan), overlaps bucket ----
    cudaStreamWaitEvent(s1, ev_scan, 0);
    k_gemm<<<GEMM_GRID, T, smem, s1>>>(x, whi + 0 * 8192, wlo + 0 * 8192, dis, hw, n);
    cudaEventRecord(ev_g1, s1);
    cudaStreamWaitEvent(0, ev_g1, 0);

    // ---- layer 1 pull ----
    k_pull<<<pull_grid, T>>>(rowptr, src, dis, hw, b1, nullptr, h, n, 0);

    // ---- layer 2 ----
    k_gemm<<<GEMM_GRID, T, smem>>>(h, whi + 1 * 8192, wlo + 1 * 8192, dis, hw, n);
    k_pull<<<pull_grid, T>>>(rowptr, src, dis, hw, b2, h, h, n, 1);

    // ---- layer 3 (fused with logits head) ----
    k_gemm<<<GEMM_GRID, T, smem>>>(h, whi + 2 * 8192, wlo + 2 * 8192, dis, hw, n);
    k_pull_logits<<<pull_grid, T>>>(rowptr, src, dis, hw, b3, h, lw, lb, out, n);
}